// round 16
// baseline (speedup 1.0000x reference)
#include <cuda_runtime.h>
#include <cuda_fp16.h>
#include <math.h>
#include <stdint.h>

#define DIMV 512
#define BATCH 8
#define QROWS 1024   // QS*QT = 64*16
#define KROWS 4096   // KS*KT = 256*16
#define RANKV 32

// ---------------- scratch (device globals; no allocation allowed) ----------------
__device__ float g_gb[BATCH * 2 * DIMV];            // gamma | beta per batch
__device__ float g_hp[BATCH * 8 * DIMV];            // ctx h partial sums
__device__ __half g_qh[BATCH * QROWS * DIMV];       // LN+FiLM(q) fp16
__device__ __half g_sh[BATCH * KROWS * DIMV];       // LN(s) fp16
__device__ __half g_ch[BATCH * QROWS * DIMV];       // attn ctx fp16
__device__ __half g_wt[4 * DIMV * DIMV];            // W^T fp16 (q,k,v,o) [n][k]
__device__ __half g_wgt[2 * 128 * DIMV];            // composite gate W^T fp16; rows>=32 stay 0
__device__ float g_gbias[2 * 128];                  // composite gate bias (r<32 valid)
__device__ __half g_qph[BATCH * QROWS * DIMV];      // q projection fp16
__device__ __half g_kph[BATCH * KROWS * DIMV];      // k projection fp16
__device__ __half g_vph[BATCH * KROWS * DIMV];      // v projection fp16
__device__ float g_gq2[BATCH * QROWS * 128];        // gate_q (cols 0..31 valid)
__device__ float g_gk2[BATCH * KROWS * 128];        // gate_k

__device__ __forceinline__ uint32_t smem_u32(const void* p) {
    uint32_t a;
    asm("{ .reg .u64 t; cvta.to.shared.u64 t, %1; cvt.u32.u64 %0, t; }" : "=r"(a) : "l"(p));
    return a;
}
__device__ __forceinline__ void cp16(uint32_t s, const void* g) {
    asm volatile("cp.async.cg.shared.global [%0], [%1], 16;" :: "r"(s), "l"(g));
}
__device__ __forceinline__ void cp_commit() {
    asm volatile("cp.async.commit_group;" ::: "memory");
}
__device__ __forceinline__ void cp_wait0() {
    asm volatile("cp.async.wait_group 0;" ::: "memory");
}
__device__ __forceinline__ void cp_wait1() {
    asm volatile("cp.async.wait_group 1;" ::: "memory");
}
__device__ __forceinline__ void ldm_x4(uint32_t* r, uint32_t addr) {
    asm volatile("ldmatrix.sync.aligned.m8n8.x4.shared.b16 {%0,%1,%2,%3}, [%4];"
                 : "=r"(r[0]), "=r"(r[1]), "=r"(r[2]), "=r"(r[3]) : "r"(addr));
}
__device__ __forceinline__ void ldm_x4_trans(uint32_t* r, uint32_t addr) {
    asm volatile("ldmatrix.sync.aligned.m8n8.x4.trans.shared.b16 {%0,%1,%2,%3}, [%4];"
                 : "=r"(r[0]), "=r"(r[1]), "=r"(r[2]), "=r"(r[3]) : "r"(addr));
}
__device__ __forceinline__ void mma16816(float* c, const uint32_t* a, uint32_t b0, uint32_t b1) {
    asm volatile(
        "mma.sync.aligned.m16n8k16.row.col.f32.f16.f16.f32 "
        "{%0,%1,%2,%3}, {%4,%5,%6,%7}, {%8,%9}, {%0,%1,%2,%3};"
        : "+f"(c[0]), "+f"(c[1]), "+f"(c[2]), "+f"(c[3])
        : "r"(a[0]), "r"(a[1]), "r"(a[2]), "r"(a[3]), "r"(b0), "r"(b1));
}

__device__ __forceinline__ float warp_sum(float v) {
    #pragma unroll
    for (int o = 16; o; o >>= 1) v += __shfl_xor_sync(0xffffffffu, v, o);
    return v;
}

// ---------------- prep: z<4 weight transpose; z==4 gate composite; z==5 ctx h partials ----------------
__global__ void prep_kernel(const float* __restrict__ Wq, const float* __restrict__ Wk,
                            const float* __restrict__ Wv, const float* __restrict__ Wo,
                            const float* __restrict__ Wgq, const float* __restrict__ Wgk,
                            const float* __restrict__ bq, const float* __restrict__ bk,
                            const float* __restrict__ ctx0, const float* __restrict__ ctx1,
                            const float* __restrict__ Wc0, const float* __restrict__ Wc1) {
    int tx = threadIdx.x, ty = threadIdx.y;   // (32, 8)
    if (blockIdx.z < 4) {
        __shared__ float t[32][33];
        const float* W = (blockIdx.z == 0) ? Wq : (blockIdx.z == 1) ? Wk
                       : (blockIdx.z == 2) ? Wv : Wo;
        __half* wt = g_wt + (size_t)blockIdx.z * DIMV * DIMV;
        int n0 = blockIdx.x * 32, k0 = blockIdx.y * 32;
        for (int r = ty; r < 32; r += 8)
            t[r][tx] = W[(size_t)(k0 + r) * DIMV + n0 + tx];
        __syncthreads();
        for (int r = ty; r < 32; r += 8)
            wt[(size_t)(n0 + r) * DIMV + k0 + tx] = __float2half(t[tx][r]);
    } else if (blockIdx.z == 4) {
        int bb = blockIdx.y * 16 + blockIdx.x;   // 0..255
        int mat = bb >> 7;                        // 0 = q, 1 = k
        const float* W  = mat ? Wk : Wq;
        const float* Wg = mat ? Wgk : Wgq;
        int t = ty * 32 + tx;
        if (t < 128) {
            int k = (bb & 127) * 4 + (t >> 5);
            int r = t & 31;
            float acc = 0.f;
            #pragma unroll 4
            for (int j = 0; j < DIMV; j++)
                acc += W[(size_t)k * DIMV + j] * Wg[j * RANKV + r];
            g_wgt[(size_t)mat * 128 * DIMV + (size_t)r * DIMV + k] = __float2half(acc);
        }
        if ((bb & 127) == 0 && t < 32) {
            const float* b = mat ? bk : bq;
            float ba = 0.f;
            #pragma unroll 4
            for (int j = 0; j < DIMV; j++) ba += b[j] * Wg[j * RANKV + t];
            g_gbias[mat * 128 + t] = ba;
        }
    } else {
        int bb = blockIdx.y * 16 + blockIdx.x;
        if (bb >= 64) return;
        int b = bb >> 3, ic = bb & 7;
        int t = ty * 32 + tx;
        int i0 = ic * 64;
        float a0 = 0.f, a1 = 0.f;
        #pragma unroll 4
        for (int i = i0; i < i0 + 64; i++) {
            float cv0 = ctx0[b * DIMV + i], cv1 = ctx1[b * DIMV + i];
            a0 += cv0 * Wc0[(size_t)i * DIMV + t] + cv1 * Wc1[(size_t)i * DIMV + t];
            a1 += cv0 * Wc0[(size_t)i * DIMV + t + 256] + cv1 * Wc1[(size_t)i * DIMV + t + 256];
        }
        g_hp[(size_t)(b * 8 + ic) * DIMV + t] = a0;
        g_hp[(size_t)(b * 8 + ic) * DIMV + t + 256] = a1;
    }
}

// ---------------- ctx phase 2: reduce partials + silu, then gamma/beta ----------------
__global__ void ctxb_kernel(const float* __restrict__ bc0, const float* __restrict__ bc1,
                            const float* __restrict__ Wf, const float* __restrict__ bf) {
    int jc = blockIdx.x, b = blockIdx.y;
    int t = threadIdx.x;   // 256
    __shared__ float h[DIMV];
    __shared__ float part[2][128];
    #pragma unroll
    for (int d = t; d < DIMV; d += 256) {
        float s = bc0[d] + bc1[d];
        #pragma unroll
        for (int ic = 0; ic < 8; ic++) s += g_hp[(size_t)(b * 8 + ic) * DIMV + d];
        h[d] = s / (1.f + expf(-s));
    }
    __syncthreads();
    int j = jc * 128 + (t & 127);
    int ih = t >> 7;
    float p = 0.f;
    #pragma unroll 4
    for (int i = ih * 256; i < ih * 256 + 256; i++)
        p += h[i] * Wf[(size_t)i * 2 * DIMV + j];
    part[ih][t & 127] = p;
    __syncthreads();
    if (t < 128)
        g_gb[b * 2 * DIMV + j] = part[0][t] + part[1][t] + bf[j];
}

// ---------------- layernorm (+FiLM for q segment) -> fp16; 2 rows per warp ----------------
__global__ void ln_kernel(const float* __restrict__ xq, const float* __restrict__ xs,
                          const float* __restrict__ qg, const float* __restrict__ qb,
                          const float* __restrict__ sg, const float* __restrict__ sb) {
    int w = threadIdx.x >> 5, lane = threadIdx.x & 31;
    int film = blockIdx.x < 512;
    const float* x = film ? xq : xs;
    const float* gw = film ? qg : sg;
    const float* bw = film ? qb : sb;
    __half* oh = film ? g_qh : g_sh;
    int row0 = (film ? blockIdx.x : (blockIdx.x - 512)) * 16 + w * 2;
    float4 v[2][4];
    float s[2] = {0.f, 0.f}, ss[2] = {0.f, 0.f};
    #pragma unroll
    for (int r = 0; r < 2; r++) {
        const float* xr = x + (size_t)(row0 + r) * DIMV;
        #pragma unroll
        for (int j = 0; j < 4; j++) {
            v[r][j] = *(const float4*)(xr + lane * 4 + j * 128);
            s[r] += v[r][j].x + v[r][j].y + v[r][j].z + v[r][j].w;
            ss[r] += v[r][j].x * v[r][j].x + v[r][j].y * v[r][j].y
                   + v[r][j].z * v[r][j].z + v[r][j].w * v[r][j].w;
        }
    }
    #pragma unroll
    for (int r = 0; r < 2; r++) { s[r] = warp_sum(s[r]); ss[r] = warp_sum(ss[r]); }
    #pragma unroll
    for (int r = 0; r < 2; r++) {
        int row = row0 + r;
        float mu = s[r] * (1.f / DIMV);
        float var = ss[r] * (1.f / DIMV) - mu * mu;
        float rstd = rsqrtf(var + 1e-5f);
        const float* gam = g_gb + (film ? (row >> 10) * 2 * DIMV : 0);
        #pragma unroll
        for (int j = 0; j < 4; j++) {
            int d = lane * 4 + j * 128;
            float vv[4] = { v[r][j].x, v[r][j].y, v[r][j].z, v[r][j].w };
            __half h[4];
            #pragma unroll
            for (int c = 0; c < 4; c++) {
                float y = (vv[c] - mu) * rstd * gw[d + c] + bw[d + c];
                if (film) y = y * (1.f + gam[d + c]) + gam[DIMV + d + c];
                h[c] = __float2half(y);
            }
            __half2* ph = (__half2*)(oh + (size_t)row * DIMV + d);
            ph[0] = __half2{h[0], h[1]};
            ph[1] = __half2{h[2], h[3]};
        }
    }
}

// ---------------- mma.sync fp16 GEMM: CTA tile 128x128, 3-stage, 2 CTAs/SM ----------------
#define BK 64
#define T_B 16384
#define STG 32768
#define GEMM_SMEM (3 * STG)      // 96 KB -> 2 CTAs/SM
#define NCHUNK 8

__global__ void __launch_bounds__(256, 2) mma_gemm(
    const __half* a0, const __half* b0, const float* bias0, void* out0, int nt0, int tpm0, int f0,
    const __half* a1, const __half* b1, const float* bias1, void* out1, int nt1, int tpm1, int f1,
    const __half* a2, const __half* b2, const float* bias2, void* out2, int f2,
    const __half* wgt, const float* gbias, float* gq2, float* gk2)
{
    extern __shared__ char smem[];
    const uint32_t sbase = smem_u32(smem);
    int tid = threadIdx.x;
    int wid = tid >> 5, lane = tid & 31;

    int id = blockIdx.x;
    const __half *A, *B;
    const float* bias; void* outp;
    int mt, nt, ostride, ocol0, ofp16;
    if (id < nt0) {
        A = a0; mt = id / tpm0; nt = id % tpm0;
        if (nt < 4) { B = b0 + (size_t)nt * 128 * DIMV; bias = bias0; outp = out0; ostride = DIMV; ocol0 = nt * 128; ofp16 = f0; }
        else        { B = wgt; bias = gbias; outp = gq2; ostride = 128; ocol0 = 0; ofp16 = 0; }
    } else if (id < nt0 + nt1) {
        int t = id - nt0;
        A = a1; mt = t / tpm1; nt = t % tpm1;
        if (nt < 4) { B = b1 + (size_t)nt * 128 * DIMV; bias = bias1; outp = out1; ostride = DIMV; ocol0 = nt * 128; ofp16 = f1; }
        else        { B = wgt + (size_t)128 * DIMV; bias = gbias + 128; outp = gk2; ostride = 128; ocol0 = 0; ofp16 = 0; }
    } else {
        int t = id - nt0 - nt1;
        A = a2; mt = t >> 2; nt = t & 3;
        B = b2 + (size_t)nt * 128 * DIMV; bias = bias2; outp = out2; ostride = DIMV; ocol0 = nt * 128; ofp16 = f2;
    }
    size_t mrow0 = (size_t)mt * 128;

    int lrow = tid >> 3;
    int lseg = tid & 7;
    uint32_t soff[4];
    #pragma unroll
    for (int i = 0; i < 4; i++) {
        uint32_t off = (lrow + i * 32) * 128 + lseg * 16;
        soff[i] = off ^ ((off >> 3) & 0x70);
    }

    int wm = wid & 3, wn = wid >> 2;
    int arow0 = wm * 32 + (lane & 15);
    uint32_t aKby = (lane >> 4) << 4;
    uint32_t axor = (arow0 & 7) << 4;
    int brow0 = wn * 64 + ((lane >> 4) << 3) + (lane & 7);
    uint32_t bKby = ((lane >> 3) & 1) << 4;
    uint32_t bxor = (brow0 & 7) << 4;

    float acc[2][8][4];
    #pragma unroll
    for (int t = 0; t < 2; t++)
        #pragma unroll
        for (int n = 0; n < 8; n++)
            #pragma unroll
            for (int j = 0; j < 4; j++) acc[t][n][j] = 0.f;

    #define LOAD_CHUNK(c, s) do {                                              \
        uint32_t dst = sbase + (s) * STG;                                      \
        int k0_ = (c) * BK;                                                    \
        _Pragma("unroll")                                                      \
        for (int i = 0; i < 4; i++) {                                          \
            cp16(dst + soff[i], A + (mrow0 + lrow + i * 32) * DIMV + k0_ + lseg * 8); \
            cp16(dst + T_B + soff[i], B + (size_t)(lrow + i * 32) * DIMV + k0_ + lseg * 8); \
        }                                                                      \
        cp_commit();                                                           \
    } while (0)

    LOAD_CHUNK(0, 0);
    LOAD_CHUNK(1, 1);

    for (int c = 0; c < NCHUNK; c++) {
        if (c == NCHUNK - 1) cp_wait0(); else cp_wait1();
        __syncthreads();
        if (c + 2 < NCHUNK) {
            int s = (c + 2) % 3;
            LOAD_CHUNK(c + 2, s);
        }
        uint32_t st = sbase + (c % 3) * STG;
        #pragma unroll
        for (int ks = 0; ks < 4; ks++) {
            uint32_t a[2][4], b[4][4];
            #pragma unroll
            for (int t = 0; t < 2; t++)
                ldm_x4(a[t], st + (uint32_t)(arow0 + t * 16) * 128 + ((ks * 32 + aKby) ^ axor));
            #pragma unroll
            for (int p = 0; p < 4; p++)
                ldm_x4(b[p], st + T_B + (uint32_t)(brow0 + p * 16) * 128 + ((ks * 32 + bKby) ^ bxor));
            #pragma unroll
            for (int t = 0; t < 2; t++)
                #pragma unroll
                for (int n = 0; n < 8; n++)
                    mma16816(acc[t][n], a[t], b[n >> 1][(n & 1) * 2], b[n >> 1][(n & 1) * 2 + 1]);
        }
    }

    int gate = (ostride == 128);
    #pragma unroll
    for (int t = 0; t < 2; t++) {
        size_t row = mrow0 + wm * 32 + t * 16 + (lane >> 2);
        #pragma unroll
        for (int n = 0; n < 8; n++) {
            if (gate && (wn != 0 || n >= 4)) continue;
            int col = ocol0 + wn * 64 + n * 8 + (lane & 3) * 2;
            float2 b2 = *(const float2*)(bias + col);
            if (ofp16) {
                __half* op = (__half*)outp;
                *(__half2*)(op + row * ostride + col) =
                    __floats2half2_rn(acc[t][n][0] + b2.x, acc[t][n][1] + b2.y);
                *(__half2*)(op + (row + 8) * ostride + col) =
                    __floats2half2_rn(acc[t][n][2] + b2.x, acc[t][n][3] + b2.y);
            } else {
                float* op = (float*)outp;
                float2 o0 = { acc[t][n][0] + b2.x, acc[t][n][1] + b2.y };
                float2 o1 = { acc[t][n][2] + b2.x, acc[t][n][3] + b2.y };
                *(float2*)(op + row * ostride + col) = o0;
                *(float2*)(op + (row + 8) * ostride + col) = o1;
            }
        }
    }
}

// ---------------- block-sparse attention: HMMA scores + HMMA AV ----------------
// Phase 1 smem: Ks 4x[144x128B] @0..73728, qs 4x[16x128B] @73728..81920,
//               gk @81920 (144x33 f32), gq @100928 (16x32 f32), sc @102976 (16x145 f32)
// Phase 2 smem (reuses dead regions): V buf0 @0, V buf1 @39168 (144x272B each),
//               P16 @78336 (16 rows x 336B)
#define OFFA_KS 0
#define OFFA_QS 73728
#define OFFA_GK 81920
#define OFFA_GQ 100928
#define OFFA_SC 102976
#define ATTN_SMEM 112256
#define SC_STRIDE 145
#define GK_STRIDE 33
#define VBUF_B 39168     // 144 * 272
#define OFF_P16 78336    // 16 * 336 = 5376

__global__ void __launch_bounds__(256, 2) attn_kernel(const float* __restrict__ mask) {
    extern __shared__ char smb[];
    const uint32_t sbase = smem_u32(smb);
    float* gqs = (float*)(smb + OFFA_GQ);
    float* gks = (float*)(smb + OFFA_GK);
    float* sc  = (float*)(smb + OFFA_SC);
    __half* p16 = (__half*)(smb + OFF_P16);

    int qs = blockIdx.x;   // 0..63
    int bb = blockIdx.y;   // 0..7
    int tid = threadIdx.x; // 256
    int wid = tid >> 5, lane = tid & 31;
    __shared__ int s_lo, s_hi;
    if (tid == 0) { s_lo = 256; s_hi = -1; }
    __syncthreads();
    {
        float mv = mask[(size_t)(qs * 16) * KROWS + tid * 16];
        if (mv == 0.0f) { atomicMin(&s_lo, tid); atomicMax(&s_hi, tid); }
    }
    __syncthreads();
    int kbase = s_lo * 16;
    int nk = (s_hi - s_lo + 1) * 16;   // multiple of 16, <= 144
    int ngroups = nk >> 4;

    size_t qrow0 = (size_t)bb * QROWS + qs * 16;
    size_t krow0 = (size_t)bb * KROWS + kbase;
    const __half* qph = g_qph + qrow0 * DIMV;
    const __half* kph = g_kph + krow0 * DIMV;
    const float SCALE = 0.04419417382415922f;   // 512^-0.5
    const float GSCALE = 0.17677669529663687f;  // 32^-0.5

    // stage gate vectors (fp32)
    for (int i = tid; i < 16 * 32; i += 256)
        gqs[i] = g_gq2[(qrow0 + (i >> 5)) * 128 + (i & 31)];
    for (int i = tid; i < nk * 32; i += 256) {
        int row = i >> 5, r = i & 31;
        gks[row * GK_STRIDE + r] = g_gk2[(krow0 + row) * 128 + r];
    }

    // fragment geometry (pitch 128B, xor swizzled)
    int arow0 = lane & 15;
    uint32_t aKby = (lane >> 4) << 4;
    uint32_t axor = (arow0 & 7) << 4;
    int brlane = ((lane >> 4) << 3) + (lane & 7);
    uint32_t bKby = ((lane >> 3) & 1) << 4;

    float acc[2][2][4];
    #pragma unroll
    for (int g = 0; g < 2; g++)
        #pragma unroll
        for (int t = 0; t < 2; t++)
            #pragma unroll
            for (int j = 0; j < 4; j++) acc[g][t][j] = 0.f;

    for (int h = 0; h < 2; h++) {
        __syncthreads();
        for (int i = tid; i < nk * 32; i += 256) {
            int row = i >> 5, seg = i & 31;
            int c = seg >> 3, s8 = seg & 7;
            uint4 v = *(const uint4*)(kph + (size_t)row * DIMV + h * 256 + c * 64 + s8 * 8);
            uint32_t off = row * 128 + s8 * 16;
            off ^= (off >> 3) & 0x70;
            *(uint4*)(smb + OFFA_KS + c * 18432 + off) = v;
        }
        for (int i = tid; i < 16 * 32; i += 256) {
            int row = i >> 5, seg = i & 31;
            int c = seg >> 3, s8 = seg & 7;
            uint4 v = *(const uint4*)(qph + (size_t)row * DIMV + h * 256 + c * 64 + s8 * 8);
            uint32_t off = row * 128 + s8 * 16;
            off ^= (off >> 3) & 0x70;
            *(uint4*)(smb + OFFA_QS + c * 2048 + off) = v;
        }
        if (h == 0) {
            for (int i = tid; i < 16 * 144; i += 256) {
                int qi = i / 144, kj = i - qi * 144;
                if (kj < nk) {
                    float gl = 0.f;
                    const float* gq = gqs + qi * 32;
                    const float* gk = gks + kj * GK_STRIDE;
                    #pragma unroll
                    for (int r = 0; r < 32; r += 4)
                        gl += gq[r] * gk[r] + gq[r+1] * gk[r+1]
                            + gq[r+2] * gk[r+2] + gq[r+3] * gk[r+3];
                    gl *= GSCALE;
                    sc[qi * SC_STRIDE + kj] = logf(1.f / (1.f + expf(-gl)) + 1e-6f);
                }
            }
        }
        __syncthreads();
        #pragma unroll
        for (int c = 0; c < 4; c++) {
            uint32_t base_k = sbase + OFFA_KS + c * 18432;
            uint32_t base_q = sbase + OFFA_QS + c * 2048;
            #pragma unroll
            for (int ks = 0; ks < 4; ks++) {
                uint32_t a[4];
                ldm_x4(a, base_q + (uint32_t)arow0 * 128 + ((ks * 32 + aKby) ^ axor));
                #pragma unroll
                for (int gi = 0; gi < 2; gi++) {
                    int g = (gi == 0) ? wid : 8;
                    if (gi == 1 && (wid != 0 || ngroups < 9)) continue;
                    if (g >= ngroups) continue;
                    int brow = g * 16 + brlane;
                    uint32_t bxor = (brow & 7) << 4;
                    uint32_t b[4];
                    ldm_x4(b, base_k + (uint32_t)brow * 128 + ((ks * 32 + bKby) ^ bxor));
                    mma16816(acc[gi][0], a, b[0], b[1]);
                    mma16816(acc[gi][1], a, b[2], b[3]);
                }
            }
        }
    }
    // store scores: sc = s*SCALE + gate_bias
    {
        int r0 = lane >> 2;
        #pragma unroll
        for (int gi = 0; gi < 2; gi++) {
            int g = (gi == 0) ? wid : 8;
            if (gi == 1 && (wid != 0 || ngroups < 9)) continue;
            if (g >= ngroups) continue;
            #pragma unroll
            for (int t = 0; t < 2; t++) {
                int col = g * 16 + t * 8 + (lane & 3) * 2;
                sc[r0 * SC_STRIDE + col]       = acc[gi][t][0] * SCALE + sc[r0 * SC_STRIDE + col];
                sc[r0 * SC_STRIDE + col + 1]   = acc[gi][t][1] * SCALE + sc[r0 * SC_STRIDE + col + 1];
                sc[(r0+8) * SC_STRIDE + col]   = acc[gi][t][2] * SCALE + sc[(r0+8) * SC_STRIDE + col];
                sc[(r0+8) * SC_STRIDE + col+1] = acc[gi][t][3] * SCALE + sc[(r0+8) * SC_STRIDE + col + 1];
            }
        }
    }
    __syncthreads();

    // issue V chunk 0 staging (into buf 0 over dead Ks region) before softmax
    const __half* vbase = g_vph + krow0 * DIMV;
    #define STAGE_V(dc, b) do {                                                 \
        const __half* vs = vbase + (dc) * 128;                                  \
        for (int i = tid; i < nk * 16; i += 256) {                              \
            int row = i >> 4, u = i & 15;                                       \
            cp16(sbase + (b) * VBUF_B + row * 272 + u * 16,                     \
                 vs + (size_t)row * DIMV + u * 8);                              \
        }                                                                       \
        cp_commit();                                                            \
    } while (0)
    STAGE_V(0, 0);

    // softmax: tx over kj, ty over qi; writes P fp16 [16][kj] stride 168 halves
    int tx = tid & 15, ty = tid >> 4;
    {
        float m = -1e30f;
        for (int kj2 = tx; kj2 < nk; kj2 += 16) m = fmaxf(m, sc[ty * SC_STRIDE + kj2]);
        #pragma unroll
        for (int o = 8; o; o >>= 1) m = fmaxf(m, __shfl_xor_sync(0xffffffffu, m, o, 16));
        float sum = 0.f;
        for (int kj2 = tx; kj2 < nk; kj2 += 16) {
            float e = expf(sc[ty * SC_STRIDE + kj2] - m);
            sc[ty * SC_STRIDE + kj2] = e;
            sum += e;
        }
        #pragma unroll
        for (int o = 8; o; o >>= 1) sum += __shfl_xor_sync(0xffffffffu, sum, o, 16);
        float inv = 1.f / sum;
        for (int kj2 = tx; kj2 < nk; kj2 += 16)
            p16[ty * 168 + kj2] = __float2half(sc[ty * SC_STRIDE + kj2] * inv);
    }
    __syncthreads();

    // AV via HMMA: 4 dim-chunks of 128; 8 warps x 16 dims; double-buffered V
    {
        __half* ch = g_ch + qrow0 * DIMV;
        int ksteps = nk >> 4;
        uint32_t pbase = sbase + OFF_P16;
        int vrow = (lane & 7) + ((lane >> 3) & 1) * 8;   // kj within step tile
        int vcol = (wid * 16 + (lane >> 4) * 8) * 2;     // byte offset of dim block
        for (int dc = 0; dc < 4; dc++) {
            cp_wait0();
            __syncthreads();
            if (dc + 1 < 4) STAGE_V(dc + 1, (dc + 1) & 1);
            uint32_t vb = sbase + (dc & 1) * VBUF_B;
            float av[2][4] = {};
            for (int ks2 = 0; ks2 < ksteps; ks2++) {
                uint32_t a[4], b[4];
                ldm_x4(a, pbase + (uint32_t)arow0 * 336 + ks2 * 32 + aKby);
                ldm_x4_trans(b, vb + (uint32_t)(ks2 * 16 + vrow) * 272 + vcol);
                mma16816(av[0], a, b[0], b[1]);
                mma16816(av[1], a, b[2], b[3]);
            }
            int r0 = lane >> 2, c2 = (lane & 3) * 2;
            #pragma unroll
            for (int g = 0; g < 2; g++) {
                int d = dc * 128 + wid * 16 + g * 8 + c2;
                *(__half2*)(ch + (size_t)r0 * DIMV + d) = __floats2half2_rn(av[g][0], av[g][1]);
                *(__half2*)(ch + (size_t)(r0 + 8) * DIMV + d) = __floats2half2_rn(av[g][2], av[g][3]);
            }
        }
    }
}

extern "C" void kernel_launch(void* const* d_in, const int* in_sizes, int n_in,
                              void* d_out, int out_size) {
    const float* query = (const float*)d_in[0];
    const float* source = (const float*)d_in[1];
    const float* ctx0  = (const float*)d_in[2];
    const float* ctx1  = (const float*)d_in[3];
    const float* mask  = (const float*)d_in[4];
    const float* qn_g  = (const float*)d_in[5];
    const float* qn_b  = (const float*)d_in[6];
    const float* kvn_g = (const float*)d_in[7];
    const float* kvn_b = (const float*)d_in[8];
    const float* Wq = (const float*)d_in[9];
    const float* bq = (const float*)d_in[10];
    const float* Wk = (const float*)d_in[11];
    const float* bk = (const float*)d_in[12];
    const float* Wv = (const float*)d_in[13];
    const float* bv = (const float*)d_in[14];
    const float* Wo = (const float*)d_in[15];
    const float* bo = (const float*)d_in[16];
    const float* Wgq = (const float*)d_in[17];
    const float* Wgk = (const float*)d_in[18];
    const float* Wc0 = (const float*)d_in[19];
    const float* bc0 = (const float*)d_in[20];
    const float* Wc1 = (const float*)d_in[21];
    const float* bc1 = (const float*)d_in[22];
    const float* Wf = (const float*)d_in[23];
    const float* bf = (const float*)d_in[24];
    float* out = (float*)d_out;

    __half *qh, *sh, *ch, *wt, *wgt, *qph, *kph, *vph;
    float *gq2, *gk2, *gbias;
    cudaGetSymbolAddress((void**)&qh, g_qh);
    cudaGetSymbolAddress((void**)&sh, g_sh);
    cudaGetSymbolAddress((void**)&ch, g_ch);
    cudaGetSymbolAddress((void**)&wt, g_wt);
    cudaGetSymbolAddress((void**)&wgt, g_wgt);
    cudaGetSymbolAddress((void**)&qph, g_qph);
    cudaGetSymbolAddress((void**)&kph, g_kph);
    cudaGetSymbolAddress((void**)&vph, g_vph);
    cudaGetSymbolAddress((void**)&gq2, g_gq2);
    cudaGetSymbolAddress((void**)&gk2, g_gk2);
    cudaGetSymbolAddress((void**)&gbias, g_gbias);

    cudaFuncSetAttribute(mma_gemm, cudaFuncAttributeMaxDynamicSharedMemorySize, GEMM_SMEM);
    cudaFuncSetAttribute(attn_kernel, cudaFuncAttributeMaxDynamicSharedMemorySize, ATTN_SMEM);

    const size_t WSZ = (size_t)DIMV * DIMV;

    prep_kernel<<<dim3(16, 16, 6), dim3(32, 8)>>>(Wq, Wk, Wv, Wo, Wgq, Wgk, bq, bk,
                                                  ctx0, ctx1, Wc0, Wc1);
    ctxb_kernel<<<dim3(8, 8), 256>>>(bc0, bc1, Wf, bf);
    ln_kernel<<<2560, 256>>>(query, source, qn_g, qn_b, kvn_g, kvn_b);
    mma_gemm<<<2624, 256, GEMM_SMEM>>>(
        qh, wt + 0 * WSZ, bq, (void*)qph, 320, 5, 1,
        sh, wt + 1 * WSZ, bk, (void*)kph, 1280, 5, 1,
        sh, wt + 2 * WSZ, bv, (void*)vph, 1,
        wgt, gbias, gq2, gk2);
    attn_kernel<<<dim3(64, BATCH), 256, ATTN_SMEM>>>(mask);
    mma_gemm<<<256, 256, GEMM_SMEM>>>(
        ch, wt + 3 * WSZ, bo, (void*)out, 256, 4, 0,
        (const __half*)0, (const __half*)0, (const float*)0, (void*)0, 0, 4, 0,
        (const __half*)0, (const __half*)0, (const float*)0, (void*)0, 0,
        wgt, gbias, gq2, gk2);
}